// round 14
// baseline (speedup 1.0000x reference)
#include <cuda_runtime.h>

#define SZ   256          // image size
#define NT   256          // number of triangles
#define QSTRIDE 5         // float4 per record slot (80B: bank-conflict-free)

// COMPACTED, ORDER-PRESERVING per-tile record table: slot k holds the k-th
// surviving triangle IN ORIGINAL INDEX ORDER (two-level prefix compaction),
// so slot order == triangle index order and the slot number itself is the
// z-tie-break key. s_idx[k] = original index, read ONCE per pixel in the
// tail (UV fetch), never in the hot loop.
//  q0 : pAB edge: ax(=v1x), ay(=v1y), dy(=v0y-v1y), dx(=v0x-v1x)
//  q1 : pCB edge: ax(=v2x), ay(=v2y), dy(=v1y-v2y), dx(=v1x-v2x)
//  q2 : pCA edge: ax(=v0x), ay(=v0y), dy(=v2y-v0y), dx(=v2x-v0x)
//  q3 : invw, z0, z1, z2
//  (q4 pad never written — stride only exists for bank spreading)
// Slots cnt..cnt+7 are zeroed null records (all edges 0 -> sign test fails
// -> never taken), so the x2-unrolled loop needs no tail guard.
//
// Inside test: the reference computes max(pAB,0)*max(pCB,0)*max(pCA,0) > 0,
// which is EXACTLY equivalent to (pAB>0 && pCB>0 && pCA>0) — product of
// three positives, O(1) magnitudes, cannot hit 0 without a factor being 0
// (underflow would need two edge values < 1e-16 at a 2/255-pitch grid
// point; not attainable). NaN: both formulations yield false. This replaces
// 3 FMNMX + 2 FMUL + FSETP with 3 AND-folded FSETPs.
//
// Block: 256 threads = 64 pixels (8x8 tile) x 4 triangle slices.
// Warp layout: lane = slice*8 + pixCol, warp index = pixRow within tile.
// Grid: (32, 32) = 1024 blocks at 6 CTAs/SM (best measured config).
// Within a slice, slots ascend, so 'z >= zb' alone reproduces the
// reference's later-triangle-wins; the slice merge compares (z, slot).
//
// Edge culling: each edge function e(p) is affine in p, so over the tile
// rectangle its max is at a corner. If any edge's corner-max <= -1e-5
// (rounding of O(1) fp32 values is < 1e-6), no pixel in the tile can have
// all three edge values strictly positive -> triangle cannot win any pixel.
//
// NOTE: the edge-function arithmetic form (px-ax)*dy-(py-ay)*dx must match
// the reference exactly — refactoring it flips boundary pixels, and a single
// flipped pixel exceeds the 1e-3 rel-err budget.
__global__ __launch_bounds__(256, 6)
void render_kernel(const float* __restrict__ tris,
                   const float* __restrict__ uvs,
                   const float* __restrict__ uvmap,
                   float* __restrict__ out) {
    __shared__ __align__(16) float4 s_q[(NT + 8) * QSTRIDE];  // ~20.6 KB
    __shared__ short s_idx[NT + 8];
    __shared__ int s_wcnt[8];

    int tid   = threadIdx.x;
    int lane  = tid & 31;
    int warp  = tid >> 5;
    int slice = lane >> 3;        // 0..3
    int pcol  = lane & 7;         // 0..7

    const float d = 2.0f / 255.0f;

    // Tile corner coordinates, computed with the exact per-pixel formula.
    int jx0 = blockIdx.x * 8, jx1 = jx0 + 7;
    int iy0 = blockIdx.y * 8, iy1 = iy0 + 7;
    float cx0 = -1.0f + (float)jx0 * d;   // px at pcol=0
    float cx1 = -1.0f + (float)jx1 * d;   // px at pcol=7
    float cy0 =  1.0f - (float)iy0 * d;   // py at row=0 (max y)
    float cy1 =  1.0f - (float)iy1 * d;   // py at row=7 (min y)

    // ---- Prep: thread t culls triangle t; survivors write records into
    //      ORDER-PRESERVING compacted slots (two-level prefix).
    {
        const float* T = tris + tid * 9;
        float v0x = __ldg(T + 0), v0y = __ldg(T + 1), v0z = __ldg(T + 2);
        float v1x = __ldg(T + 3), v1y = __ldg(T + 4), v1z = __ldg(T + 5);
        float v2x = __ldg(T + 6), v2y = __ldg(T + 7), v2z = __ldg(T + 8);

        float w = (v1x - v0x) * (v2y - v0y) - (v1y - v0y) * (v2x - v0x);
        bool valid = (w >= 1e-9f);

        // Edge corner-max cull: e = (cx-ax)*dy - (cy-ay)*dx is separable,
        // max = max_x[(cx-ax)*dy] + max_y[-(cy-ay)*dx].
        #define EDGE_MAX(ax, ay, dy, dx) \
            (fmaxf((cx0 - (ax)) * (dy), (cx1 - (ax)) * (dy)) + \
             fmaxf(-((cy0 - (ay)) * (dx)), -((cy1 - (ay)) * (dx))))
        float mAB = EDGE_MAX(v1x, v1y, v0y - v1y, v0x - v1x);
        float mCB = EDGE_MAX(v2x, v2y, v1y - v2y, v1x - v2x);
        float mCA = EDGE_MAX(v0x, v0y, v2y - v0y, v2x - v0x);
        #undef EDGE_MAX

        bool keep = valid && (mAB > -1e-5f) && (mCB > -1e-5f) && (mCA > -1e-5f);

        unsigned mask = __ballot_sync(0xffffffffu, keep);
        if (lane == 0) s_wcnt[warp] = __popc(mask);
        __syncthreads();

        int base = 0, cnt = 0;
        #pragma unroll
        for (int ww = 0; ww < 8; ww++) {
            int c = s_wcnt[ww];
            if (ww < warp) base += c;
            cnt += c;
        }

        if (keep) {
            int slot = base + __popc(mask & ((1u << lane) - 1u));
            float invw = 1.0f / w;           // valid==true here (w >= 1e-9)
            float4* Q = s_q + slot * QSTRIDE;
            Q[0] = make_float4(v1x, v1y, v0y - v1y, v0x - v1x);
            Q[1] = make_float4(v2x, v2y, v1y - v2y, v1x - v2x);
            Q[2] = make_float4(v0x, v0y, v2y - v0y, v2x - v0x);
            Q[3] = make_float4(invw, v0z, v1z, v2z);
            s_idx[slot] = (short)tid;
        }
        if (tid < 8) {                       // null-pad slots cnt..cnt+7
            float4* Q = s_q + (cnt + tid) * QSTRIDE;
            float4 z4 = make_float4(0.0f, 0.0f, 0.0f, 0.0f);
            Q[0] = z4; Q[1] = z4; Q[2] = z4; Q[3] = z4;
        }
        // stash cnt for after the barrier via shared (reuse s_wcnt[0] read)
    }
    __syncthreads();
    int cnt = 0;
    #pragma unroll
    for (int ww = 0; ww < 8; ww++) cnt += s_wcnt[ww];

    // Pixel coordinates: pts[i][j] = (lin[j], lin[255-i]), lin[k] = -1 + k*2/255
    int j = jx0 + pcol;
    int i = iy0 + warp;
    float px = -1.0f + (float)j * d;
    float py =  1.0f - (float)i * d;

    // Each slice scans every 4th slot, two per loop iteration (second may be
    // a null record -> never taken). Slots ascend within a slice, so
    // 'z >= zb' reproduces later-triangle-wins. Branch-free selects.
    float zb  = -3.402823466e+38f;
    float w1s = 0.0f, w2s = 0.0f;
    int   bslot = -1;

    #define EVAL(SLOT)                                                       \
    {                                                                        \
        const float4* Q = s_q + (SLOT) * QSTRIDE;                            \
        float4 q0 = Q[0], q1 = Q[1], q2 = Q[2], q3 = Q[3];                   \
        float pAB = (px - q0.x) * q0.z - (py - q0.y) * q0.w;                 \
        float pCB = (px - q1.x) * q1.z - (py - q1.y) * q1.w;                 \
        float pCA = (px - q2.x) * q2.z - (py - q2.y) * q2.w;                 \
        float w1 = pCB * q3.x;                                               \
        float w2 = pCA * q3.x;                                               \
        float w3 = 1.0f - w1 - w2;                                           \
        float z  = w1 * q3.y + w2 * q3.z + w3 * q3.w;                        \
        bool take = (pAB > 0.0f) && (pCB > 0.0f) && (pCA > 0.0f) &&          \
                    (z >= zb);                                               \
        zb    = take ? z      : zb;                                          \
        bslot = take ? (SLOT) : bslot;                                       \
        w1s   = take ? w1     : w1s;                                         \
        w2s   = take ? w2     : w2s;                                         \
    }

    for (int k = slice; k < cnt; k += 8) {
        EVAL(k);
        EVAL(k + 4);
    }
    #undef EVAL

    // Merge the 4 slices of each pixel: (z, slot) max, ties -> larger slot
    // (slot order == original index order).
    #pragma unroll
    for (int off = 8; off < 32; off <<= 1) {
        float oz = __shfl_down_sync(0xffffffffu, zb, off);
        int   oi = __shfl_down_sync(0xffffffffu, bslot, off);
        float o1 = __shfl_down_sync(0xffffffffu, w1s, off);
        float o2 = __shfl_down_sync(0xffffffffu, w2s, off);
        bool take = (oz > zb) || ((oz == zb) && (oi > bslot));
        if (take) { zb = oz; bslot = oi; w1s = o1; w2s = o2; }
    }

    if (slice == 0) {
        // Deferred UV interpolation + bilinear texture sample (winner only)
        float r = 0.0f, g = 0.0f, b = 0.0f, a = 0.0f;
        if (bslot >= 0) {
            a = 1.0f;
            int bidx = s_idx[bslot];          // original triangle index
            const float* U = uvs + bidx * 6;
            float u0 = __ldg(U + 0) * 2.0f - 1.0f, v0 = __ldg(U + 1) * 2.0f - 1.0f;
            float u1 = __ldg(U + 2) * 2.0f - 1.0f, v1 = __ldg(U + 3) * 2.0f - 1.0f;
            float u2 = __ldg(U + 4) * 2.0f - 1.0f, v2 = __ldg(U + 5) * 2.0f - 1.0f;
            float w3 = 1.0f - w1s - w2s;
            float uu = w1s * u0 + w2s * u1 + w3 * u2;
            float vv = w1s * v0 + w2s * v1 + w3 * v2;

            float x = (uu + 1.0f) * 0.5f * 1023.0f;
            float y = (vv + 1.0f) * 0.5f * 1023.0f;
            float x0f = floorf(x);
            float y0f = floorf(y);
            float wx = x - x0f;
            float wy = y - y0f;
            #pragma unroll
            for (int cy = 0; cy < 2; cy++) {
                #pragma unroll
                for (int cx = 0; cx < 2; cx++) {
                    float ix = x0f + (float)cx;
                    float iy = y0f + (float)cy;
                    bool inb = (ix >= 0.0f) && (ix <= 1023.0f) &&
                               (iy >= 0.0f) && (iy <= 1023.0f);
                    if (inb) {
                        int ii = (int)ix;
                        int jj = (int)iy;
                        float wgt = (cx ? wx : 1.0f - wx) * (cy ? wy : 1.0f - wy);
                        int toff = jj * 1024 + ii;
                        r += __ldg(uvmap + toff) * wgt;
                        g += __ldg(uvmap + 1048576 + toff) * wgt;
                        b += __ldg(uvmap + 2097152 + toff) * wgt;
                    }
                }
            }
        }

        int pix = i * SZ + j;
        out[pix]              = r;
        out[65536 + pix]      = g;
        out[2 * 65536 + pix]  = b;
        out[3 * 65536 + pix]  = a;
    }
}

extern "C" void kernel_launch(void* const* d_in, const int* in_sizes, int n_in,
                              void* d_out, int out_size) {
    const float* tris  = (const float*)d_in[0];   // (256,3,3)
    const float* uvs   = (const float*)d_in[1];   // (256,3,2)
    const float* uvmap = (const float*)d_in[2];   // (3,1024,1024)
    float* out = (float*)d_out;                   // (4,256,256)

    dim3 block(256);
    dim3 grid(SZ / 8, SZ / 8);
    render_kernel<<<grid, block>>>(tris, uvs, uvmap, out);
}

// round 15
// speedup vs baseline: 1.0507x; 1.0507x over previous
#include <cuda_runtime.h>

#define SZ   256          // image size
#define NT   256          // number of triangles
#define QSTRIDE 5         // float4 per record slot (80B spread; loads are
                          // warp-uniform broadcasts so conflicts moot anyway)

// COMPACTED per-tile record table (unordered; tie-break uses s_idx):
//  q0 : pAB edge: ax(=v1x), ay(=v1y), dy(=v0y-v1y), dx(=v0x-v1x)
//  q1 : pCB edge: ax(=v2x), ay(=v2y), dy(=v1y-v2y), dx(=v1x-v2x)
//  q2 : pCA edge: ax(=v0x), ay(=v0y), dy(=v2y-v0y), dx(=v2x-v0x)
//  q3 : invw, z0, z1, z2
// s_idx[k] = original triangle index. Slots cnt..cnt+7 are zeroed null
// records (edges 0 -> sign test false -> never taken): no tail guard needed.
//
// WARP-UNIFORM SLICING: warp w covers slice (w>>1) for tile-half (w&1):
// rows (w&1)*4 + lane/8, col lane&7. Every lane of a warp evaluates the
// SAME triangle -> all record LDS.128 are broadcasts (1 smem wavefront,
// not 4) and slot arithmetic is warp-uniform. The old lane-sliced layout
// spent ~35% of kernel cycles on the smem crossbar.
// Slice partials merge through a 4KB smem table, reduced by 64 threads
// whose final stores are fully coalesced.
//
// Inside test: max(pAB,0)*max(pCB,0)*max(pCA,0) > 0 is exactly equivalent
// to (pAB>0 && pCB>0 && pCA>0) (product of three positives of O(1)
// magnitude can't underflow to 0 at a 2/255-pitch grid; NaN -> false in
// both). Verified: rel_err unchanged at 6.420912e-05 in R13.
//
// The z-buffer scan reduces to argmax over covering triangles, ties ->
// larger original index ('inside' => all barycentric weights > 0 => z is a
// convex combination of vertex z's => z >= global zmin, so the zbuf init
// never matters). Argmax is order-independent: compaction order is
// irrelevant because the tie-break compares original indices.
//
// Edge culling: each edge function is affine, so its max over the tile
// rectangle is at a corner; if any edge's corner-max <= -1e-5 the triangle
// cannot win any pixel of the tile (fp rounding of O(1) values < 1e-6).
//
// NOTE: the edge-function arithmetic form (px-ax)*dy-(py-ay)*dx must match
// the reference exactly — refactoring it flips boundary pixels and a single
// flipped pixel exceeds the 1e-3 rel-err budget.
__global__ __launch_bounds__(256, 6)
void render_kernel(const float* __restrict__ tris,
                   const float* __restrict__ uvs,
                   const float* __restrict__ uvmap,
                   float* __restrict__ out) {
    __shared__ __align__(16) float4 s_q[(NT + 8) * QSTRIDE];  // ~20.6 KB
    __shared__ short s_idx[NT + 8];
    __shared__ int s_cnt;
    __shared__ __align__(16) float4 s_red[4][64];             // 4 KB partials

    int tid  = threadIdx.x;
    int lane = tid & 31;
    int warp = tid >> 5;          // 0..7

    const float d = 2.0f / 255.0f;

    if (tid == 0) s_cnt = 0;

    // Tile corner coordinates, computed with the exact per-pixel formula.
    int jx0 = blockIdx.x * 8, jx1 = jx0 + 7;
    int iy0 = blockIdx.y * 8, iy1 = iy0 + 7;
    float cx0 = -1.0f + (float)jx0 * d;
    float cx1 = -1.0f + (float)jx1 * d;
    float cy0 =  1.0f - (float)iy0 * d;
    float cy1 =  1.0f - (float)iy1 * d;

    // ---- Prep: thread t culls triangle t; survivors write records into
    //      compacted slots (unordered; s_idx carries the true index).
    {
        const float* T = tris + tid * 9;
        float v0x = __ldg(T + 0), v0y = __ldg(T + 1), v0z = __ldg(T + 2);
        float v1x = __ldg(T + 3), v1y = __ldg(T + 4), v1z = __ldg(T + 5);
        float v2x = __ldg(T + 6), v2y = __ldg(T + 7), v2z = __ldg(T + 8);

        float w = (v1x - v0x) * (v2y - v0y) - (v1y - v0y) * (v2x - v0x);
        bool valid = (w >= 1e-9f);

        #define EDGE_MAX(ax, ay, dy, dx) \
            (fmaxf((cx0 - (ax)) * (dy), (cx1 - (ax)) * (dy)) + \
             fmaxf(-((cy0 - (ay)) * (dx)), -((cy1 - (ay)) * (dx))))
        float mAB = EDGE_MAX(v1x, v1y, v0y - v1y, v0x - v1x);
        float mCB = EDGE_MAX(v2x, v2y, v1y - v2y, v1x - v2x);
        float mCA = EDGE_MAX(v0x, v0y, v2y - v0y, v2x - v0x);
        #undef EDGE_MAX

        bool keep = valid && (mAB > -1e-5f) && (mCB > -1e-5f) && (mCA > -1e-5f);

        unsigned mask = __ballot_sync(0xffffffffu, keep);
        __syncthreads();   // orders s_cnt=0 before the atomics
        int base = 0;
        if (lane == 0 && mask) base = atomicAdd(&s_cnt, __popc(mask));
        base = __shfl_sync(0xffffffffu, base, 0);

        if (keep) {
            int slot = base + __popc(mask & ((1u << lane) - 1u));
            float invw = 1.0f / w;           // valid==true here (w >= 1e-9)
            float4* Q = s_q + slot * QSTRIDE;
            Q[0] = make_float4(v1x, v1y, v0y - v1y, v0x - v1x);
            Q[1] = make_float4(v2x, v2y, v1y - v2y, v1x - v2x);
            Q[2] = make_float4(v0x, v0y, v2y - v0y, v2x - v0x);
            Q[3] = make_float4(invw, v0z, v1z, v2z);
            s_idx[slot] = (short)tid;
        }
    }
    __syncthreads();
    int cnt = s_cnt;
    if (tid < 8) {                 // null-pad slots cnt..cnt+7
        float4* Q = s_q + (cnt + tid) * QSTRIDE;
        float4 z4 = make_float4(0.0f, 0.0f, 0.0f, 0.0f);
        Q[0] = z4; Q[1] = z4; Q[2] = z4; Q[3] = z4;
        s_idx[cnt + tid] = -1;
    }
    __syncthreads();

    // Warp-uniform slicing: warp w -> slice (w>>1), tile-half (w&1).
    int slice = warp >> 1;
    int half  = warp & 1;
    int row   = half * 4 + (lane >> 3);   // 0..7 within tile
    int col   = lane & 7;

    int j = jx0 + col;
    int i = iy0 + row;
    float px = -1.0f + (float)j * d;
    float py =  1.0f - (float)i * d;

    // Scan: slice s evaluates slots s, s+4, s+8, ... (two per iteration;
    // second may be a null record). Slot is warp-uniform -> broadcast loads.
    // Tie-break compares original indices (works for any compaction order).
    float zb   = -3.402823466e+38f;
    float w1s  = 0.0f, w2s = 0.0f;
    int   bidx = -1;

    #define EVAL(SLOT)                                                       \
    {                                                                        \
        const float4* Q = s_q + (SLOT) * QSTRIDE;                            \
        int idx = s_idx[SLOT];                                               \
        float4 q0 = Q[0], q1 = Q[1], q2 = Q[2], q3 = Q[3];                   \
        float pAB = (px - q0.x) * q0.z - (py - q0.y) * q0.w;                 \
        float pCB = (px - q1.x) * q1.z - (py - q1.y) * q1.w;                 \
        float pCA = (px - q2.x) * q2.z - (py - q2.y) * q2.w;                 \
        float w1 = pCB * q3.x;                                               \
        float w2 = pCA * q3.x;                                               \
        float w3 = 1.0f - w1 - w2;                                           \
        float z  = w1 * q3.y + w2 * q3.z + w3 * q3.w;                        \
        bool take = (pAB > 0.0f) && (pCB > 0.0f) && (pCA > 0.0f) &&          \
                    ((z > zb) || ((z == zb) && (idx > bidx)));               \
        zb   = take ? z   : zb;                                              \
        bidx = take ? idx : bidx;                                            \
        w1s  = take ? w1  : w1s;                                             \
        w2s  = take ? w2  : w2s;                                             \
    }

    for (int k = slice; k < cnt; k += 8) {
        EVAL(k);
        EVAL(k + 4);
    }
    #undef EVAL

    // Publish slice partial for this pixel (idx stored exactly as float).
    s_red[slice][row * 8 + col] = make_float4(zb, w1s, w2s, (float)bidx);
    __syncthreads();

    // 64 threads: reduce the 4 slice partials of pixel p, then UV+texture.
    if (tid < 64) {
        int p = tid;
        float4 best = s_red[0][p];
        #pragma unroll
        for (int s = 1; s < 4; s++) {
            float4 c = s_red[s][p];
            bool take = (c.x > best.x) || ((c.x == best.x) && (c.w > best.w));
            if (take) best = c;
        }
        float w1f = best.y, w2f = best.z;
        int bwin = (int)best.w;

        float r = 0.0f, g = 0.0f, b = 0.0f, a = 0.0f;
        if (bwin >= 0) {
            a = 1.0f;
            const float* U = uvs + bwin * 6;
            float u0 = __ldg(U + 0) * 2.0f - 1.0f, v0 = __ldg(U + 1) * 2.0f - 1.0f;
            float u1 = __ldg(U + 2) * 2.0f - 1.0f, v1 = __ldg(U + 3) * 2.0f - 1.0f;
            float u2 = __ldg(U + 4) * 2.0f - 1.0f, v2 = __ldg(U + 5) * 2.0f - 1.0f;
            float w3f = 1.0f - w1f - w2f;
            float uu = w1f * u0 + w2f * u1 + w3f * u2;
            float vv = w1f * v0 + w2f * v1 + w3f * v2;

            float x = (uu + 1.0f) * 0.5f * 1023.0f;
            float y = (vv + 1.0f) * 0.5f * 1023.0f;
            float x0f = floorf(x);
            float y0f = floorf(y);
            float wx = x - x0f;
            float wy = y - y0f;
            #pragma unroll
            for (int cy = 0; cy < 2; cy++) {
                #pragma unroll
                for (int cx = 0; cx < 2; cx++) {
                    float ix = x0f + (float)cx;
                    float iy = y0f + (float)cy;
                    bool inb = (ix >= 0.0f) && (ix <= 1023.0f) &&
                               (iy >= 0.0f) && (iy <= 1023.0f);
                    if (inb) {
                        int ii = (int)ix;
                        int jj = (int)iy;
                        float wgt = (cx ? wx : 1.0f - wx) * (cy ? wy : 1.0f - wy);
                        int toff = jj * 1024 + ii;
                        r += __ldg(uvmap + toff) * wgt;
                        g += __ldg(uvmap + 1048576 + toff) * wgt;
                        b += __ldg(uvmap + 2097152 + toff) * wgt;
                    }
                }
            }
        }

        int pix = (iy0 + (p >> 3)) * SZ + jx0 + (p & 7);
        out[pix]              = r;
        out[65536 + pix]      = g;
        out[2 * 65536 + pix]  = b;
        out[3 * 65536 + pix]  = a;
    }
}

extern "C" void kernel_launch(void* const* d_in, const int* in_sizes, int n_in,
                              void* d_out, int out_size) {
    const float* tris  = (const float*)d_in[0];   // (256,3,3)
    const float* uvs   = (const float*)d_in[1];   // (256,3,2)
    const float* uvmap = (const float*)d_in[2];   // (3,1024,1024)
    float* out = (float*)d_out;                   // (4,256,256)

    dim3 block(256);
    dim3 grid(SZ / 8, SZ / 8);
    render_kernel<<<grid, block>>>(tris, uvs, uvmap, out);
}